// round 1
// baseline (speedup 1.0000x reference)
#include <cuda_runtime.h>
#include <cuda_bf16.h>

#define NN 10000
#define IN_F 128
#define OUT_F 64
#define EDGES 320000
#define ALPHA 0.2f
#define BITWORDS 3125000   // ceil(NN*NN / 32)

// ---------------- scratch (device globals; no allocation allowed) -----------
__device__ unsigned      g_bitmap[BITWORDS];     // 12.5 MB dedup bitmap
__device__ int           g_deg[NN + 1];
__device__ int           g_rowstart[NN + 1];
__device__ int           g_cursor[NN];
__device__ unsigned char g_flag[EDGES];
__device__ int           g_cols[EDGES];
__device__ float         g_vals[EDGES];
__device__ float         g_Wh[NN * OUT_F];       // 2.56 MB
__device__ float         g_s1[NN];
__device__ float         g_s2[NN];
__device__ float         g_mean[OUT_F];
__device__ int           g_is64;

// ---------------- helpers ---------------------------------------------------
__device__ __forceinline__ int edge_src(const void* p, int e, int is64) {
    return is64 ? (int)((const long long*)p)[e] : ((const int*)p)[e];
}
__device__ __forceinline__ int edge_dst(const void* p, int e, int is64) {
    return is64 ? (int)((const long long*)p)[EDGES + e] : ((const int*)p)[EDGES + e];
}
__device__ __forceinline__ float elu_f(float x) {
    return x > 0.f ? x : expm1f(x);
}

// ---------------- 1. clear scratch -----------------------------------------
__global__ void clear_kernel() {
    int idx = blockIdx.x * blockDim.x + threadIdx.x;
    int stride = gridDim.x * blockDim.x;
    for (int i = idx; i < BITWORDS; i += stride) g_bitmap[i] = 0u;
    for (int i = idx; i <= NN; i += stride) g_deg[i] = 0;
    if (idx == 0) g_is64 = 1;
}

// ---------------- 2. detect edge_index dtype --------------------------------
// Read ONLY the first 2*E int32's worth of bytes (= E int64s) — always in-bounds.
// If the data really is int64, every one of those E values (the src row) is in
// [0, NN). If the data is int32, each int64 read combines two int32 values and
// is >= 2^32 whenever the high half is nonzero -> detection fails -> int32.
__global__ void detect_kernel(const void* ei) {
    const long long* p = (const long long*)ei;
    int idx = blockIdx.x * blockDim.x + threadIdx.x;
    int stride = gridDim.x * blockDim.x;
    bool bad = false;
    for (int i = idx; i < EDGES; i += stride) {
        long long v = p[i];
        if (v < 0 || v >= NN) bad = true;
    }
    if (bad) atomicAnd(&g_is64, 0);
}

// ---------------- 3. Wh = h @ W  (tiled) ------------------------------------
#define GEMM_BM 16
__global__ void gemm_kernel(const float* __restrict__ h, const float* __restrict__ W) {
    __shared__ float Ws[IN_F * OUT_F];        // 32 KB
    __shared__ float hs[GEMM_BM * 129];       // padded to kill bank conflicts
    int t = threadIdx.x;                      // 256 threads
    int row0 = blockIdx.x * GEMM_BM;

    for (int i = t; i < IN_F * OUT_F; i += 256) Ws[i] = W[i];
    for (int i = t; i < GEMM_BM * IN_F; i += 256) {
        int r = i / IN_F, k = i % IN_F;
        int gr = row0 + r;
        hs[r * 129 + k] = (gr < NN) ? h[gr * IN_F + k] : 0.f;
    }
    __syncthreads();

    int col = t & 63;
    int r0  = (t >> 6) * 4;                   // 4 rows per thread
    float acc0 = 0.f, acc1 = 0.f, acc2 = 0.f, acc3 = 0.f;
#pragma unroll 8
    for (int k = 0; k < IN_F; k++) {
        float w = Ws[k * OUT_F + col];
        acc0 += hs[(r0 + 0) * 129 + k] * w;
        acc1 += hs[(r0 + 1) * 129 + k] * w;
        acc2 += hs[(r0 + 2) * 129 + k] * w;
        acc3 += hs[(r0 + 3) * 129 + k] * w;
    }
    float acc[4] = {acc0, acc1, acc2, acc3};
#pragma unroll
    for (int j = 0; j < 4; j++) {
        int gr = row0 + r0 + j;
        if (gr < NN) g_Wh[gr * OUT_F + col] = acc[j];
    }
}

// ---------------- 4. s1 = Wh @ a[:64], s2 = Wh @ a[64:] ---------------------
__global__ void s_kernel(const float* __restrict__ a) {
    int gtid = blockIdx.x * blockDim.x + threadIdx.x;
    int row = gtid >> 5;
    int lane = gtid & 31;
    if (row >= NN) return;
    float v0 = g_Wh[row * OUT_F + lane];
    float v1 = g_Wh[row * OUT_F + 32 + lane];
    float p1 = v0 * a[lane] + v1 * a[lane + 32];
    float p2 = v0 * a[64 + lane] + v1 * a[96 + lane];
#pragma unroll
    for (int off = 16; off > 0; off >>= 1) {
        p1 += __shfl_xor_sync(0xFFFFFFFFu, p1, off);
        p2 += __shfl_xor_sync(0xFFFFFFFFu, p2, off);
    }
    if (lane == 0) { g_s1[row] = p1; g_s2[row] = p2; }
}

// ---------------- 5. column mean of Wh (zero-degree softmax fallback) -------
__global__ void mean_kernel() {
    __shared__ float sh[1024];
    int t = threadIdx.x;                      // 1024 threads
    int col = t & 63;
    int grp = t >> 6;                         // 16 row groups
    float s = 0.f;
    for (int r = grp; r < NN; r += 16) s += g_Wh[r * OUT_F + col];
    sh[t] = s;
    __syncthreads();
    if (t < 64) {
        float tot = 0.f;
#pragma unroll
        for (int g = 0; g < 16; g++) tot += sh[g * 64 + t];
        g_mean[t] = tot / (float)NN;
    }
}

// ---------------- 6. dedup + degree count -----------------------------------
__global__ void count_kernel(const void* ei) {
    int is64 = g_is64;
    int idx = blockIdx.x * blockDim.x + threadIdx.x;
    int stride = gridDim.x * blockDim.x;
    for (int e = idx; e < EDGES; e += stride) {
        int s = edge_src(ei, e, is64);
        int d = edge_dst(ei, e, is64);
        unsigned key = (unsigned)s * (unsigned)NN + (unsigned)d;
        unsigned bit = 1u << (key & 31u);
        unsigned old = atomicOr(&g_bitmap[key >> 5], bit);
        bool fresh = (old & bit) == 0u;
        g_flag[e] = fresh ? 1 : 0;
        if (fresh) atomicAdd(&g_deg[s], 1);
    }
}

// ---------------- 7. exclusive prefix scan (single block) -------------------
__global__ void scan_kernel() {
    __shared__ int sh[1024];
    int t = threadIdx.x;
    int carry = 0;
    for (int base = 0; base < NN; base += 1024) {
        int i = base + t;
        int v = (i < NN) ? g_deg[i] : 0;
        sh[t] = v;
        __syncthreads();
        for (int off = 1; off < 1024; off <<= 1) {
            int x = (t >= off) ? sh[t - off] : 0;
            __syncthreads();
            sh[t] += x;
            __syncthreads();
        }
        int excl = sh[t] - v;
        if (i < NN) { g_rowstart[i] = carry + excl; g_cursor[i] = carry + excl; }
        int tot = sh[1023];
        __syncthreads();
        carry += tot;
    }
    if (t == 0) g_rowstart[NN] = carry;
}

// ---------------- 8. scatter into CSR with edge weights ---------------------
__global__ void scatter_kernel(const void* ei) {
    int is64 = g_is64;
    int idx = blockIdx.x * blockDim.x + threadIdx.x;
    int stride = gridDim.x * blockDim.x;
    for (int e = idx; e < EDGES; e += stride) {
        if (!g_flag[e]) continue;
        int s = edge_src(ei, e, is64);
        int d = edge_dst(ei, e, is64);
        float x = g_s1[s] + g_s2[d];
        float lr = x > 0.f ? x : ALPHA * x;      // leaky relu
        float w = __expf(lr) + 0.f;
        w = expf(lr);                             // full-precision exp
        int pos = atomicAdd(&g_cursor[s], 1);
        g_cols[pos] = d;
        g_vals[pos] = w;
    }
}

// ---------------- 9. warp-per-row: softmax-normalize, aggregate, ELU --------
__global__ void row_kernel(float* __restrict__ out) {
    int gtid = blockIdx.x * blockDim.x + threadIdx.x;
    int row = gtid >> 5;
    int lane = gtid & 31;
    if (row >= NN) return;
    int beg = g_rowstart[row];
    int end = g_rowstart[row + 1];
    float a0 = 0.f, a1 = 0.f, sw = 0.f;
    if (beg == end) {
        // softmax over an all -inf row is uniform -> h' = column mean of Wh
        a0 = g_mean[lane];
        a1 = g_mean[lane + 32];
        sw = 1.f;
    } else {
        for (int p = beg; p < end; p++) {
            int c = g_cols[p];
            float w = g_vals[p];
            sw += w;
            a0 += w * g_Wh[c * OUT_F + lane];
            a1 += w * g_Wh[c * OUT_F + 32 + lane];
        }
    }
    float inv = 1.f / sw;
    out[row * OUT_F + lane]      = elu_f(a0 * inv);
    out[row * OUT_F + 32 + lane] = elu_f(a1 * inv);
}

// ---------------- launch ----------------------------------------------------
extern "C" void kernel_launch(void* const* d_in, const int* in_sizes, int n_in,
                              void* d_out, int out_size) {
    const float* h  = (const float*)d_in[0];
    const void*  ei = d_in[1];
    const float* W  = (const float*)d_in[2];
    const float* a  = (const float*)d_in[3];
    float* out = (float*)d_out;

    clear_kernel<<<4096, 256>>>();
    detect_kernel<<<640, 512>>>(ei);
    gemm_kernel<<<(NN + GEMM_BM - 1) / GEMM_BM, 256>>>(h, W);
    s_kernel<<<(NN * 32 + 255) / 256, 256>>>(a);
    mean_kernel<<<1, 1024>>>();
    count_kernel<<<640, 512>>>(ei);
    scan_kernel<<<1, 1024>>>();
    scatter_kernel<<<640, 512>>>(ei);
    row_kernel<<<(NN * 32 + 255) / 256, 256>>>(out);
}

// round 2
// speedup vs baseline: 1.0709x; 1.0709x over previous
#include <cuda_runtime.h>
#include <cuda_bf16.h>

#define NN 10000
#define IN_F 128
#define OUT_F 64
#define EDGES 320000
#define ALPHA 0.2f
#define MEAN_BLOCKS 40
#define ROWS_PER_MEAN_BLOCK 250   // 40 * 250 = 10000

// ---------------- scratch (device globals; no allocation allowed) -----------
__device__ int   g_deg[NN + 1];
__device__ int   g_rowstart[NN + 1];
__device__ int   g_cursor[NN];
__device__ int   g_cols[EDGES];
__device__ float g_Wh[NN * OUT_F];          // 2.56 MB (L2-resident)
__device__ float g_s1[NN];
__device__ float g_s2[NN];
__device__ float g_meanpart[MEAN_BLOCKS * OUT_F];
__device__ int   g_is64;

// ---------------- helpers ---------------------------------------------------
__device__ __forceinline__ int edge_src(const void* p, int e, int is64) {
    return is64 ? (int)((const long long*)p)[e] : ((const int*)p)[e];
}
__device__ __forceinline__ int edge_dst(const void* p, int e, int is64) {
    return is64 ? (int)((const long long*)p)[EDGES + e] : ((const int*)p)[EDGES + e];
}
__device__ __forceinline__ float elu_f(float x) {
    return x > 0.f ? x : expm1f(x);
}

// ---------------- 1. init: zero degrees, set dtype flag ---------------------
__global__ void init_kernel() {
    int idx = blockIdx.x * blockDim.x + threadIdx.x;
    if (idx <= NN) g_deg[idx] = 0;
    if (idx == 0) g_is64 = 1;
}

// ---------------- 2. detect edge_index dtype --------------------------------
// Read ONLY the first E int64s (= 2E int32s worth of bytes) — always in-bounds.
// int64 data: all E src values in [0, NN). int32 data: each int64 read packs
// two int32s -> >= 2^32 whenever the high half (another node id) is nonzero,
// which happens w.p. 1 - 1e-4 per element -> detection is certain.
__global__ void detect_kernel(const void* ei) {
    const long long* p = (const long long*)ei;
    int idx = blockIdx.x * blockDim.x + threadIdx.x;
    int stride = gridDim.x * blockDim.x;
    bool bad = false;
    for (int i = idx; i < EDGES; i += stride) {
        long long v = p[i];
        if (v < 0 || v >= NN) bad = true;
    }
    if (bad) atomicAnd(&g_is64, 0);
}

// ---------------- 3. Wh = h @ W  (tiled) ------------------------------------
#define GEMM_BM 16
__global__ void gemm_kernel(const float* __restrict__ h, const float* __restrict__ W) {
    __shared__ float Ws[IN_F * OUT_F];        // 32 KB
    __shared__ float hs[GEMM_BM * 129];       // padded to kill bank conflicts
    int t = threadIdx.x;                      // 256 threads
    int row0 = blockIdx.x * GEMM_BM;

    for (int i = t; i < IN_F * OUT_F; i += 256) Ws[i] = W[i];
    for (int i = t; i < GEMM_BM * IN_F; i += 256) {
        int r = i / IN_F, k = i % IN_F;
        int gr = row0 + r;
        hs[r * 129 + k] = (gr < NN) ? h[gr * IN_F + k] : 0.f;
    }
    __syncthreads();

    int col = t & 63;
    int r0  = (t >> 6) * 4;                   // 4 rows per thread
    float acc0 = 0.f, acc1 = 0.f, acc2 = 0.f, acc3 = 0.f;
#pragma unroll 8
    for (int k = 0; k < IN_F; k++) {
        float w = Ws[k * OUT_F + col];
        acc0 += hs[(r0 + 0) * 129 + k] * w;
        acc1 += hs[(r0 + 1) * 129 + k] * w;
        acc2 += hs[(r0 + 2) * 129 + k] * w;
        acc3 += hs[(r0 + 3) * 129 + k] * w;
    }
    float acc[4] = {acc0, acc1, acc2, acc3};
#pragma unroll
    for (int j = 0; j < 4; j++) {
        int gr = row0 + r0 + j;
        if (gr < NN) g_Wh[gr * OUT_F + col] = acc[j];
    }
}

// ---------------- 4. s1 = Wh @ a[:64], s2 = Wh @ a[64:] ---------------------
__global__ void s_kernel(const float* __restrict__ a) {
    int gtid = blockIdx.x * blockDim.x + threadIdx.x;
    int row = gtid >> 5;
    int lane = gtid & 31;
    if (row >= NN) return;
    float v0 = g_Wh[row * OUT_F + lane];
    float v1 = g_Wh[row * OUT_F + 32 + lane];
    float p1 = v0 * a[lane] + v1 * a[lane + 32];
    float p2 = v0 * a[64 + lane] + v1 * a[96 + lane];
#pragma unroll
    for (int off = 16; off > 0; off >>= 1) {
        p1 += __shfl_xor_sync(0xFFFFFFFFu, p1, off);
        p2 += __shfl_xor_sync(0xFFFFFFFFu, p2, off);
    }
    if (lane == 0) { g_s1[row] = p1; g_s2[row] = p2; }
}

// ---------------- 5. deterministic column-sum partials of Wh ----------------
// (zero-degree softmax fallback; final 40-term reduce happens in row_kernel)
__global__ void meanpart_kernel() {
    __shared__ float sh[256];
    int t = threadIdx.x;                      // 256 threads
    int col = t & 63;
    int grp = t >> 6;                         // 4 row groups
    int row0 = blockIdx.x * ROWS_PER_MEAN_BLOCK;
    float s = 0.f;
    for (int r = row0 + grp; r < row0 + ROWS_PER_MEAN_BLOCK; r += 4)
        s += g_Wh[r * OUT_F + col];
    sh[t] = s;
    __syncthreads();
    if (t < 64) {
        float tot = sh[t] + sh[64 + t] + sh[128 + t] + sh[192 + t];
        g_meanpart[blockIdx.x * OUT_F + t] = tot;
    }
}

// ---------------- 6. degree count (with duplicates) -------------------------
__global__ void count_kernel(const void* ei) {
    int is64 = g_is64;
    int idx = blockIdx.x * blockDim.x + threadIdx.x;
    int stride = gridDim.x * blockDim.x;
    for (int e = idx; e < EDGES; e += stride) {
        int s = edge_src(ei, e, is64);
        atomicAdd(&g_deg[s], 1);
    }
}

// ---------------- 7. exclusive prefix scan (1 block, shuffle-based) ---------
#define SCAN_PT 10   // 1024 threads * 10 = 10240 >= NN
__global__ void scan_kernel() {
    __shared__ int wsum[32];
    int t = threadIdx.x;
    int lane = t & 31, wid = t >> 5;
    int base = t * SCAN_PT;
    int v[SCAN_PT];
    int s = 0;
#pragma unroll
    for (int i = 0; i < SCAN_PT; i++) {
        int idx = base + i;
        int x = (idx < NN) ? g_deg[idx] : 0;
        v[i] = s;                              // thread-local exclusive
        s += x;
    }
    // inclusive warp scan of per-thread sums
    int inc = s;
#pragma unroll
    for (int off = 1; off < 32; off <<= 1) {
        int y = __shfl_up_sync(0xFFFFFFFFu, inc, off);
        if (lane >= off) inc += y;
    }
    if (lane == 31) wsum[wid] = inc;
    __syncthreads();
    if (wid == 0) {
        int x = wsum[lane];
        int ix = x;
#pragma unroll
        for (int off = 1; off < 32; off <<= 1) {
            int y = __shfl_up_sync(0xFFFFFFFFu, ix, off);
            if (lane >= off) ix += y;
        }
        wsum[lane] = ix - x;                   // exclusive warp base
    }
    __syncthreads();
    int tbase = wsum[wid] + (inc - s);         // exclusive prefix for this thread
#pragma unroll
    for (int i = 0; i < SCAN_PT; i++) {
        int idx = base + i;
        if (idx < NN) {
            g_rowstart[idx] = tbase + v[i];
            g_cursor[idx]   = tbase + v[i];
        }
    }
    if (t == 1023) g_rowstart[NN] = tbase + s; // grand total (= EDGES)
}

// ---------------- 8. scatter dst ids into CSR (dups included) ---------------
__global__ void scatter_kernel(const void* ei) {
    int is64 = g_is64;
    int idx = blockIdx.x * blockDim.x + threadIdx.x;
    int stride = gridDim.x * blockDim.x;
    for (int e = idx; e < EDGES; e += stride) {
        int s = edge_src(ei, e, is64);
        int d = edge_dst(ei, e, is64);
        int pos = atomicAdd(&g_cursor[s], 1);
        g_cols[pos] = d;
    }
}

// ---------------- 9. warp-per-row: dedup, softmax, aggregate, ELU -----------
__global__ void row_kernel(float* __restrict__ out) {
    int gtid = blockIdx.x * blockDim.x + threadIdx.x;
    int row = gtid >> 5;
    int lane = gtid & 31;
    if (row >= NN) return;
    int beg = g_rowstart[row];
    int end = g_rowstart[row + 1];
    float a0 = 0.f, a1 = 0.f, swl = 0.f;
    float s1r = g_s1[row];

    for (int p0 = beg; p0 < end; p0 += 32) {
        int p = p0 + lane;
        int c = -1;
        float w = 0.f;
        if (p < end) {
            c = g_cols[p];
            // keep only the FIRST occurrence of each dst within this row
            bool keep = true;
            for (int q = beg; q < p; q++)
                if (g_cols[q] == c) { keep = false; break; }
            if (keep) {
                float x = s1r + g_s2[c];
                float lr = x > 0.f ? x : ALPHA * x;   // leaky relu
                w = expf(lr);
                swl += w;
            } else {
                c = -1;
            }
        }
        int cnt = end - p0; if (cnt > 32) cnt = 32;
        for (int j = 0; j < cnt; j++) {
            int cc = __shfl_sync(0xFFFFFFFFu, c, j);
            float ww = __shfl_sync(0xFFFFFFFFu, w, j);
            if (cc >= 0) {
                a0 += ww * g_Wh[cc * OUT_F + lane];
                a1 += ww * g_Wh[cc * OUT_F + 32 + lane];
            }
        }
    }
    // warp-reduce the weight sum
    float sw = swl;
#pragma unroll
    for (int off = 16; off > 0; off >>= 1)
        sw += __shfl_xor_sync(0xFFFFFFFFu, sw, off);

    if (beg == end) {
        // softmax over all -inf row is uniform -> h' = column mean of Wh
        float m0 = 0.f, m1 = 0.f;
        for (int b = 0; b < MEAN_BLOCKS; b++) {
            m0 += g_meanpart[b * OUT_F + lane];
            m1 += g_meanpart[b * OUT_F + 32 + lane];
        }
        a0 = m0 / (float)NN;
        a1 = m1 / (float)NN;
        sw = 1.f;
    }
    float inv = 1.f / sw;
    out[row * OUT_F + lane]      = elu_f(a0 * inv);
    out[row * OUT_F + 32 + lane] = elu_f(a1 * inv);
}

// ---------------- launch ----------------------------------------------------
extern "C" void kernel_launch(void* const* d_in, const int* in_sizes, int n_in,
                              void* d_out, int out_size) {
    const float* h  = (const float*)d_in[0];
    const void*  ei = d_in[1];
    const float* W  = (const float*)d_in[2];
    const float* a  = (const float*)d_in[3];
    float* out = (float*)d_out;

    init_kernel<<<(NN + 256) / 256, 256>>>();
    detect_kernel<<<640, 512>>>(ei);
    gemm_kernel<<<(NN + GEMM_BM - 1) / GEMM_BM, 256>>>(h, W);
    s_kernel<<<(NN * 32 + 255) / 256, 256>>>(a);
    meanpart_kernel<<<MEAN_BLOCKS, 256>>>();
    count_kernel<<<640, 512>>>(ei);
    scan_kernel<<<1, 1024>>>();
    scatter_kernel<<<640, 512>>>(ei);
    row_kernel<<<(NN * 32 + 255) / 256, 256>>>(out);
}

// round 3
// speedup vs baseline: 3.6485x; 3.4069x over previous
#include <cuda_runtime.h>
#include <cuda_bf16.h>

#define NN 10000
#define IN_F 128
#define OUT_F 64
#define EDGES 320000
#define ALPHA 0.2f
#define MEAN_BLOCKS 40
#define ROWS_PER_MEAN_BLOCK 250   // 40 * 250 = 10000

// ---------------- scratch (device globals; no allocation allowed) -----------
__device__ int   g_deg[NN + 1];
__device__ int   g_rowstart[NN + 1];
__device__ int   g_cursor[NN];
__device__ int   g_cols[EDGES];
__device__ float g_Wh[NN * OUT_F];          // 2.56 MB (L2-resident)
__device__ float g_s1[NN];
__device__ float g_s2[NN];
__device__ float g_meanpart[MEAN_BLOCKS * OUT_F];
__device__ int   g_is64;

// ---------------- helpers ---------------------------------------------------
__device__ __forceinline__ int edge_src(const void* p, int e, int is64) {
    return is64 ? (int)((const long long*)p)[e] : ((const int*)p)[e];
}
__device__ __forceinline__ int edge_dst(const void* p, int e, int is64) {
    return is64 ? (int)((const long long*)p)[EDGES + e] : ((const int*)p)[EDGES + e];
}
__device__ __forceinline__ float elu_f(float x) {
    return x > 0.f ? x : expm1f(x);
}

// ---------------- 1. init: zero degrees, set dtype flag ---------------------
__global__ void init_kernel() {
    int idx = blockIdx.x * blockDim.x + threadIdx.x;
    if (idx <= NN) g_deg[idx] = 0;
    if (idx == 0) g_is64 = 1;
}

// ---------------- 2. detect edge_index dtype --------------------------------
// Read ONLY the first E int64s (= 2E int32s worth of bytes) — always in-bounds.
// int64 data: all E src values are in [0, NN). int32 data: each int64 read
// packs two int32 node ids -> >= 2^32 whenever the high half is nonzero
// (probability 1 - 1e-4 PER ELEMENT) -> detection certain within each thread's
// first couple of elements.
//
// CRITICAL (round-2 lesson): in the int32 case EVERY thread sees bad=true.
// 327k atomicAnd to one address serializes at ~0.854 cyc/lane => ~160us.
// Instead: early-break + warp ballot + one PLAIN store per warp (benign race,
// all writers store the same value 0).
__global__ void detect_kernel(const void* ei) {
    const long long* p = (const long long*)ei;
    int idx = blockIdx.x * blockDim.x + threadIdx.x;
    int stride = gridDim.x * blockDim.x;
    bool bad = false;
    for (int i = idx; i < EDGES; i += stride) {
        long long v = p[i];
        if (v < 0 || v >= NN) { bad = true; break; }
    }
    unsigned m = __ballot_sync(0xFFFFFFFFu, bad);
    if (m != 0u && (threadIdx.x & 31) == 0) g_is64 = 0;
}

// ---------------- 3. Wh = h @ W  (tiled) ------------------------------------
#define GEMM_BM 16
__global__ void gemm_kernel(const float* __restrict__ h, const float* __restrict__ W) {
    __shared__ float Ws[IN_F * OUT_F];        // 32 KB
    __shared__ float hs[GEMM_BM * 129];       // padded to kill bank conflicts
    int t = threadIdx.x;                      // 256 threads
    int row0 = blockIdx.x * GEMM_BM;

    for (int i = t; i < IN_F * OUT_F; i += 256) Ws[i] = W[i];
    for (int i = t; i < GEMM_BM * IN_F; i += 256) {
        int r = i / IN_F, k = i % IN_F;
        int gr = row0 + r;
        hs[r * 129 + k] = (gr < NN) ? h[gr * IN_F + k] : 0.f;
    }
    __syncthreads();

    int col = t & 63;
    int r0  = (t >> 6) * 4;                   // 4 rows per thread
    float acc0 = 0.f, acc1 = 0.f, acc2 = 0.f, acc3 = 0.f;
#pragma unroll 8
    for (int k = 0; k < IN_F; k++) {
        float w = Ws[k * OUT_F + col];
        acc0 += hs[(r0 + 0) * 129 + k] * w;
        acc1 += hs[(r0 + 1) * 129 + k] * w;
        acc2 += hs[(r0 + 2) * 129 + k] * w;
        acc3 += hs[(r0 + 3) * 129 + k] * w;
    }
    float acc[4] = {acc0, acc1, acc2, acc3};
#pragma unroll
    for (int j = 0; j < 4; j++) {
        int gr = row0 + r0 + j;
        if (gr < NN) g_Wh[gr * OUT_F + col] = acc[j];
    }
}

// ---------------- 4. s1 = Wh @ a[:64], s2 = Wh @ a[64:] ---------------------
__global__ void s_kernel(const float* __restrict__ a) {
    int gtid = blockIdx.x * blockDim.x + threadIdx.x;
    int row = gtid >> 5;
    int lane = gtid & 31;
    if (row >= NN) return;
    float v0 = g_Wh[row * OUT_F + lane];
    float v1 = g_Wh[row * OUT_F + 32 + lane];
    float p1 = v0 * a[lane] + v1 * a[lane + 32];
    float p2 = v0 * a[64 + lane] + v1 * a[96 + lane];
#pragma unroll
    for (int off = 16; off > 0; off >>= 1) {
        p1 += __shfl_xor_sync(0xFFFFFFFFu, p1, off);
        p2 += __shfl_xor_sync(0xFFFFFFFFu, p2, off);
    }
    if (lane == 0) { g_s1[row] = p1; g_s2[row] = p2; }
}

// ---------------- 5. deterministic column-sum partials of Wh ----------------
// (zero-degree softmax fallback; final 40-term reduce happens in row_kernel)
__global__ void meanpart_kernel() {
    __shared__ float sh[256];
    int t = threadIdx.x;                      // 256 threads
    int col = t & 63;
    int grp = t >> 6;                         // 4 row groups
    int row0 = blockIdx.x * ROWS_PER_MEAN_BLOCK;
    float s = 0.f;
    for (int r = row0 + grp; r < row0 + ROWS_PER_MEAN_BLOCK; r += 4)
        s += g_Wh[r * OUT_F + col];
    sh[t] = s;
    __syncthreads();
    if (t < 64) {
        float tot = sh[t] + sh[64 + t] + sh[128 + t] + sh[192 + t];
        g_meanpart[blockIdx.x * OUT_F + t] = tot;
    }
}

// ---------------- 6. degree count (with duplicates) -------------------------
__global__ void count_kernel(const void* ei) {
    int is64 = g_is64;
    int idx = blockIdx.x * blockDim.x + threadIdx.x;
    int stride = gridDim.x * blockDim.x;
    for (int e = idx; e < EDGES; e += stride) {
        int s = edge_src(ei, e, is64);
        atomicAdd(&g_deg[s], 1);
    }
}

// ---------------- 7. exclusive prefix scan (1 block, shuffle-based) ---------
#define SCAN_PT 10   // 1024 threads * 10 = 10240 >= NN
__global__ void scan_kernel() {
    __shared__ int wsum[32];
    int t = threadIdx.x;
    int lane = t & 31, wid = t >> 5;
    int base = t * SCAN_PT;
    int v[SCAN_PT];
    int s = 0;
#pragma unroll
    for (int i = 0; i < SCAN_PT; i++) {
        int idx = base + i;
        int x = (idx < NN) ? g_deg[idx] : 0;
        v[i] = s;                              // thread-local exclusive
        s += x;
    }
    // inclusive warp scan of per-thread sums
    int inc = s;
#pragma unroll
    for (int off = 1; off < 32; off <<= 1) {
        int y = __shfl_up_sync(0xFFFFFFFFu, inc, off);
        if (lane >= off) inc += y;
    }
    if (lane == 31) wsum[wid] = inc;
    __syncthreads();
    if (wid == 0) {
        int x = wsum[lane];
        int ix = x;
#pragma unroll
        for (int off = 1; off < 32; off <<= 1) {
            int y = __shfl_up_sync(0xFFFFFFFFu, ix, off);
            if (lane >= off) ix += y;
        }
        wsum[lane] = ix - x;                   // exclusive warp base
    }
    __syncthreads();
    int tbase = wsum[wid] + (inc - s);         // exclusive prefix for this thread
#pragma unroll
    for (int i = 0; i < SCAN_PT; i++) {
        int idx = base + i;
        if (idx < NN) {
            g_rowstart[idx] = tbase + v[i];
            g_cursor[idx]   = tbase + v[i];
        }
    }
    if (t == 1023) g_rowstart[NN] = tbase + s; // grand total (= EDGES)
}

// ---------------- 8. scatter dst ids into CSR (dups included) ---------------
__global__ void scatter_kernel(const void* ei) {
    int is64 = g_is64;
    int idx = blockIdx.x * blockDim.x + threadIdx.x;
    int stride = gridDim.x * blockDim.x;
    for (int e = idx; e < EDGES; e += stride) {
        int s = edge_src(ei, e, is64);
        int d = edge_dst(ei, e, is64);
        int pos = atomicAdd(&g_cursor[s], 1);
        g_cols[pos] = d;
    }
}

// ---------------- 9. warp-per-row: dedup, softmax, aggregate, ELU -----------
__global__ void row_kernel(float* __restrict__ out) {
    int gtid = blockIdx.x * blockDim.x + threadIdx.x;
    int row = gtid >> 5;
    int lane = gtid & 31;
    if (row >= NN) return;
    int beg = g_rowstart[row];
    int end = g_rowstart[row + 1];
    float a0 = 0.f, a1 = 0.f, swl = 0.f;
    float s1r = g_s1[row];

    for (int p0 = beg; p0 < end; p0 += 32) {
        int p = p0 + lane;
        int c = -1;
        float w = 0.f;
        if (p < end) {
            c = g_cols[p];
            // keep only the FIRST occurrence of each dst within this row
            bool keep = true;
            for (int q = beg; q < p; q++)
                if (g_cols[q] == c) { keep = false; break; }
            if (keep) {
                float x = s1r + g_s2[c];
                float lr = x > 0.f ? x : ALPHA * x;   // leaky relu
                w = expf(lr);
                swl += w;
            } else {
                c = -1;
            }
        }
        int cnt = end - p0; if (cnt > 32) cnt = 32;
        for (int j = 0; j < cnt; j++) {
            int cc = __shfl_sync(0xFFFFFFFFu, c, j);
            float ww = __shfl_sync(0xFFFFFFFFu, w, j);
            if (cc >= 0) {
                a0 += ww * g_Wh[cc * OUT_F + lane];
                a1 += ww * g_Wh[cc * OUT_F + 32 + lane];
            }
        }
    }
    // warp-reduce the weight sum
    float sw = swl;
#pragma unroll
    for (int off = 16; off > 0; off >>= 1)
        sw += __shfl_xor_sync(0xFFFFFFFFu, sw, off);

    if (beg == end) {
        // softmax over all -inf row is uniform -> h' = column mean of Wh
        float m0 = 0.f, m1 = 0.f;
        for (int b = 0; b < MEAN_BLOCKS; b++) {
            m0 += g_meanpart[b * OUT_F + lane];
            m1 += g_meanpart[b * OUT_F + 32 + lane];
        }
        a0 = m0 / (float)NN;
        a1 = m1 / (float)NN;
        sw = 1.f;
    }
    float inv = 1.f / sw;
    out[row * OUT_F + lane]      = elu_f(a0 * inv);
    out[row * OUT_F + 32 + lane] = elu_f(a1 * inv);
}

// ---------------- launch ----------------------------------------------------
extern "C" void kernel_launch(void* const* d_in, const int* in_sizes, int n_in,
                              void* d_out, int out_size) {
    const float* h  = (const float*)d_in[0];
    const void*  ei = d_in[1];
    const float* W  = (const float*)d_in[2];
    const float* a  = (const float*)d_in[3];
    float* out = (float*)d_out;

    init_kernel<<<(NN + 256) / 256, 256>>>();
    detect_kernel<<<640, 512>>>(ei);
    gemm_kernel<<<(NN + GEMM_BM - 1) / GEMM_BM, 256>>>(h, W);
    s_kernel<<<(NN * 32 + 255) / 256, 256>>>(a);
    meanpart_kernel<<<MEAN_BLOCKS, 256>>>();
    count_kernel<<<640, 512>>>(ei);
    scan_kernel<<<1, 1024>>>();
    scatter_kernel<<<640, 512>>>(ei);
    row_kernel<<<(NN * 32 + 255) / 256, 256>>>(out);
}